// round 11
// baseline (speedup 1.0000x reference)
#include <cuda_runtime.h>

// Problem constants
#define Bn     32
#define Cn     40
#define Ln     16000
#define Kn     128
#define Sn     125      // LS / STRIDE
#define STILE  32       // s-values per block
#define NTILES 4        // ceil(125/32)
#define NOUT   (Bn * Cn * Sn)   // 160000 outputs (real part)

#define XSEG   132               // 128 data + 4 pad floats per segment

// ---- packed f32x2 helpers (Blackwell sm_103a) ----
#define FMA2(acc, a, b) \
    asm("fma.rn.f32x2 %0, %1, %2, %0;" : "+l"(acc) : "l"(a), "l"(b))
#define ADD2(acc, a) \
    asm("add.rn.f32x2 %0, %0, %1;" : "+l"(acc) : "l"(a))
#define PACKDUP(out, f) \
    asm("mov.b64 %0, {%1, %1};" : "=l"(out) : "f"(f))
#define UNPACK2(lo, hi, in) \
    asm("mov.b64 {%0, %1}, %2;" : "=f"(lo), "=f"(hi) : "l"(in))

// ---------------- fast mode-0 kernel (real part only) ----------------
// Grid (4, 32), 1024 threads = 32 warps.
//   warp w: q = w>>2 (K-slice of 16 taps), g = w&3 (channel group of 10 ch
//           = 5 channel PAIRS); lane = s within 32-s tile.
// smem (ulonglong units):
//   kp   : 20 pairs x 128 taps, float2 (ch2p, ch2p+1), tap-REVERSED   (20 KB)
//   xs   : 32 segments x 132 floats (pad -> conflict-free float4)     (16.9 KB)
//   part : 8 slices x 20 pairs x 32 lanes, packed f32x2 partials      (40 KB)
#define KP_ULL    (20 * Kn)            // 2560
#define XS_ULL    ((32 * XSEG) / 2)    // 2112
#define PART_ULL  (8 * 20 * 32)        // 5120
#define SMEMB_FAST ((KP_ULL + XS_ULL + PART_ULL) * 8)   // 78336 B

__global__ __launch_bounds__(1024, 1)
void isac_conv_fast(const float* __restrict__ x,
                    const float* __restrict__ kr,
                    float* __restrict__ out)
{
    extern __shared__ unsigned long long smem_u[];
    unsigned long long* kp   = smem_u;
    float*              xs   = (float*)(smem_u + KP_ULL);
    unsigned long long* part = smem_u + KP_ULL + XS_ULL;

    const int tid   = threadIdx.x;
    const int stile = blockIdx.x;
    const int b     = blockIdx.y;

    // ---- kernel repack: kp[p][m] = (kr[2p][127-m], kr[2p+1][127-m]) ----
    {
        float2* kpf = (float2*)kp;
        #pragma unroll
        for (int i = 0; i < 3; i++) {
            const int idx = tid + i * 1024;
            if (idx < KP_ULL) {
                const int p = idx >> 7, m = idx & 127;
                kpf[idx] = make_float2(kr[(2 * p)     * Kn + (127 - m)],
                                       kr[(2 * p + 1) * Kn + (127 - m)]);
            }
        }
    }

    // ---- x tile: segment L holds x[128*(s0+L)-127 .. 128*(s0+L)] ----
    const int gstart = stile * (STILE * Kn) - 127;   // negative only for tile 0
    const float* xb = x + b * Ln;
    #pragma unroll
    for (int i = 0; i < 4; i++) {
        const int j = tid + i * 1024;
        int g = gstart + j;
        if (g < 0)        g += Ln;
        else if (g >= Ln) g -= Ln;
        xs[(j >> 7) * XSEG + (j & 127)] = xb[g];
    }
    __syncthreads();

    // ---- compute: 5 channel-pairs x 16-tap slice per thread ----
    const int lane = tid & 31;            // s within tile
    const int w    = tid >> 5;
    const int g    = w & 3;               // channel group (10 channels)
    const int q    = w >> 2;              // K slice (16 taps)
    const int pr0  = g * 5;               // first channel pair

    const float4* xp = (const float4*)(xs + lane * XSEG) + q * 4;
    // pair j taps (q*16 + t): ulonglong2 = 2 consecutive taps of one pair
    const ulonglong2* kp2 = (const ulonglong2*)kp + (pr0 * 64 + q * 8);

    unsigned long long acc[5] = {0ull, 0ull, 0ull, 0ull, 0ull};

    #pragma unroll
    for (int i = 0; i < 4; i++) {          // 4 float4 = 16 taps
        const float4 xv = xp[i];
        unsigned long long x0, x1, x2, x3;
        PACKDUP(x0, xv.x); PACKDUP(x1, xv.y);
        PACKDUP(x2, xv.z); PACKDUP(x3, xv.w);
        #pragma unroll
        for (int j = 0; j < 5; j++) {
            const ulonglong2 k01 = kp2[j * 64 + 2 * i];      // taps 4i,4i+1 (broadcast)
            const ulonglong2 k23 = kp2[j * 64 + 2 * i + 1];  // taps 4i+2,4i+3
            FMA2(acc[j], x0, k01.x);
            FMA2(acc[j], x1, k01.y);
            FMA2(acc[j], x2, k23.x);
            FMA2(acc[j], x3, k23.y);
        }
    }

    // ---- stash packed partials: part[q][pair][lane] ----
    #pragma unroll
    for (int j = 0; j < 5; j++)
        part[q * (20 * 32) + (pr0 + j) * 32 + lane] = acc[j];
    __syncthreads();

    // ---- reduce 8 K-slices, unpack, write (B, C, 125) float32 ----
    const int s0 = stile * STILE;
    if (tid < 640) {                      // 20 pairs x 32 lanes
        const int p = tid >> 5, s = tid & 31;
        unsigned long long v = part[tid];
        #pragma unroll
        for (int q2 = 1; q2 < 8; q2++)
            ADD2(v, part[q2 * 640 + tid]);
        float lo, hi;
        UNPACK2(lo, hi, v);
        if (s0 + s < Sn) {
            out[(b * Cn + 2 * p)     * Sn + (s0 + s)] = lo;
            out[(b * Cn + 2 * p + 1) * Sn + (s0 + s)] = hi;
        }
    }
}

// ---------------- fallback (full complex) — not expected to trigger ----------------
#define KERN_FLOATS (Cn * Kn)
#define SMEMB_FB ((2 * KERN_FLOATS + 32 * XSEG) * 4)

__global__ __launch_bounds__(256)
void isac_conv_fallback(const float* __restrict__ x,
                        const float* __restrict__ kr,
                        const float* __restrict__ ki,
                        float* __restrict__ out,
                        int mode)   // 1 = planar, 2 = interleaved
{
    extern __shared__ float smem[];
    float* kr_s = smem;
    float* ki_s = smem + KERN_FLOATS;
    float* xs   = smem + 2 * KERN_FLOATS;

    const int tid = threadIdx.x, stile = blockIdx.x, b = blockIdx.y;
    #pragma unroll 4
    for (int idx = tid; idx < KERN_FLOATS; idx += 256) {
        const int c = idx >> 7, m = idx & 127;
        kr_s[idx] = kr[c * Kn + (127 - m)];
        ki_s[idx] = ki[c * Kn + (127 - m)];
    }
    const int gstart = stile * (STILE * Kn) - 127;
    const float* xb = x + b * Ln;
    #pragma unroll 4
    for (int j = tid; j < 32 * Kn; j += 256) {
        int g = gstart + j;
        if (g < 0) g += Ln; else if (g >= Ln) g -= Ln;
        xs[(j >> 7) * XSEG + (j & 127)] = xb[g];
    }
    __syncthreads();

    const int lane = tid & 31, w = tid >> 5;
    const int s = stile * STILE + lane, c0 = w * 5;
    const float4* xp  = (const float4*)(xs + lane * XSEG);
    const float4* krp = (const float4*)(kr_s + c0 * Kn);
    const float4* kip = (const float4*)(ki_s + c0 * Kn);

    float ar[5] = {0,0,0,0,0}, ai[5] = {0,0,0,0,0};
    #pragma unroll 2
    for (int m4 = 0; m4 < Kn / 4; m4++) {
        const float4 xv = xp[m4];
        #pragma unroll
        for (int cc = 0; cc < 5; cc++) {
            const float4 kv = krp[cc * (Kn / 4) + m4];
            const float4 iv = kip[cc * (Kn / 4) + m4];
            ar[cc] = fmaf(xv.x, kv.x, fmaf(xv.y, kv.y, fmaf(xv.z, kv.z, fmaf(xv.w, kv.w, ar[cc]))));
            ai[cc] = fmaf(xv.x, iv.x, fmaf(xv.y, iv.y, fmaf(xv.z, iv.z, fmaf(xv.w, iv.w, ai[cc]))));
        }
    }
    if (s < Sn) {
        if (mode == 1) {
            #pragma unroll
            for (int cc = 0; cc < 5; cc++) {
                const int idx = (b * Cn + (c0 + cc)) * Sn + s;
                out[idx] = ar[cc]; out[NOUT + idx] = ai[cc];
            }
        } else {
            float2* o2 = (float2*)out;
            #pragma unroll
            for (int cc = 0; cc < 5; cc++)
                o2[(b * Cn + (c0 + cc)) * Sn + s] = make_float2(ar[cc], ai[cc]);
        }
    }
}

extern "C" void kernel_launch(void* const* d_in, const int* in_sizes, int n_in,
                              void* d_out, int out_size)
{
    const float* x  = (const float*)d_in[0];   // (32, 1, 16000) f32
    const float* kr = (const float*)d_in[1];   // (40, 128) f32
    const float* ki = (const float*)d_in[2];   // (40, 128) f32
    float* out = (float*)d_out;

    dim3 grid(NTILES, Bn);
    if (out_size == NOUT) {
        cudaFuncSetAttribute(isac_conv_fast,
                             cudaFuncAttributeMaxDynamicSharedMemorySize, SMEMB_FAST);
        isac_conv_fast<<<grid, 1024, SMEMB_FAST>>>(x, kr, out);
    } else {
        const int mode = (out_size == 2 * NOUT) ? 1 : 2;
        cudaFuncSetAttribute(isac_conv_fallback,
                             cudaFuncAttributeMaxDynamicSharedMemorySize, SMEMB_FB);
        isac_conv_fallback<<<grid, 256, SMEMB_FB>>>(x, kr, ki, out, mode);
    }
}